// round 11
// baseline (speedup 1.0000x reference)
#include <cuda_runtime.h>

// Problem shapes (fixed for this dataset entry)
#define B_   4
#define Q_   128
#define N_   50000
#define C_   20
#define BQ_  (B_ * Q_)          // 512
#define BN_  (B_ * N_)          // 200000
#define NV_  (N_ / 4)           // 12500 float4 per row
#define S_   10                 // chunks per row
#define CHUNK_ (NV_ / S_)       // 1250 float4 per chunk
#define GIDV_ (BN_ / 4)         // 50000 int4 for gid convert
#define GID_BLOCKS ((GIDV_ + 255) / 256)         // 196 blocks cover gid

#define MIN_PTS_NUM  50
#define MIN_INST_CLS 4

// Output layout (fp32 concatenation, matching reference return order)
#define OFF_SCORES ((size_t)BQ_ * N_)            // 25,600,000
#define OFF_VALID  (OFF_SCORES + BQ_)
#define OFF_CLS    (OFF_VALID + BQ_)
#define OFF_GID    (OFF_CLS + BQ_)

// Scratch (no device allocation -> __device__ globals). Partials are plain
// overwriting stores (idempotent across replays). g_arrive is incremented by
// each of a row's 10 blocks and reset to 0 by the last one -> returns to its
// initial state every invocation (graph-replay safe, deterministic).
__device__ int   g_part_cnt[BQ_][S_];
__device__ float g_part_sum[BQ_][S_];
__device__ int   g_arrive[BQ_];

// Inline per-row argmax over C=20 class logits. Matches jnp.argmax first-max.
__device__ __forceinline__ int row_argmax(const float* __restrict__ p)
{
    float best = __ldg(&p[0]);
    int bi = 0;
    #pragma unroll
    for (int c = 1; c < C_; c++) {
        float v = __ldg(&p[c]);
        if (v > best) { best = v; bi = c; }
    }
    return bi;
}

// ---------------------------------------------------------------------------
// Single fused kernel: grid (S_, BQ_). One block per 1250-float4 chunk.
//  - first 196 flattened blocks also do the gid int4->float4 convert
//  - cls<4 rows: stream zeros (no logit read), publish zero partials
//  - else: sel = (logit>0)&(seg==cls) [sigmoid(x)>0.5 <=> x>0, no MUFU for
//    select]; streaming mask write; block-reduce count + sigmoid-sum
//  - arrival protocol: thread0 fences, bumps g_arrive[bq]; the LAST of the
//    row's 10 blocks re-reads all partials (fixed order -> deterministic),
//    writes score/valid/cls, cooperatively re-zeroes the row if needed
//    (never with this data), and resets the arrival counter.
// ---------------------------------------------------------------------------
__global__ __launch_bounds__(256, 6)
void fused_kernel(const float* __restrict__ mask_logits,
                  const float* __restrict__ cls_logits,
                  const int* __restrict__ seg_pred,
                  const int* __restrict__ fg_idxs,
                  float* __restrict__ out_masks,
                  float* __restrict__ out_scores,
                  float* __restrict__ out_valid,
                  float* __restrict__ out_cls,
                  float* __restrict__ out_gid)
{
    const int chunk = blockIdx.x;
    const int bq    = blockIdx.y;
    const int fb    = bq * S_ + chunk;    // flattened block id

    // gid convert: coalesced int4 -> float4, first 196 blocks only.
    if (fb < GID_BLOCKS) {
        int vi = fb * 256 + threadIdx.x;
        if (vi < GIDV_) {
            int4 v = __ldg(&reinterpret_cast<const int4*>(fg_idxs)[vi]);
            float4 f;
            f.x = (float)v.x; f.y = (float)v.y;
            f.z = (float)v.z; f.w = (float)v.w;
            reinterpret_cast<float4*>(out_gid)[vi] = f;
        }
    }

    const int b   = bq >> 7;              // / Q_
    const int cls = row_argmax(cls_logits + bq * C_);
    const size_t base = (size_t)bq * NV_ + (size_t)chunk * CHUNK_;

    float4* __restrict__ om = reinterpret_cast<float4*>(out_masks) + base;

    if (cls < MIN_INST_CLS) {
        const float4 z = make_float4(0.f, 0.f, 0.f, 0.f);
        #pragma unroll
        for (int k = 0; k < 5; k++) {
            int i = threadIdx.x + k * 256;
            if (i < CHUNK_) __stcs(&om[i], z);
        }
        if (threadIdx.x == 0) {           // publish zero partials
            g_part_cnt[bq][chunk] = 0;
            g_part_sum[bq][chunk] = 0.f;
        }
    } else {
        const float4* __restrict__ ml = reinterpret_cast<const float4*>(mask_logits) + base;
        const int4*   __restrict__ sp = reinterpret_cast<const int4*>(seg_pred) +
                                        (size_t)b * NV_ + (size_t)chunk * CHUNK_;

        int   cnt  = 0;
        float ssum = 0.f;

        // 5 (float4, int4) pairs; k<4 bounds compile-time true (1024<1250).
        float4 x[5]; int4 s[5];
        #pragma unroll
        for (int k = 0; k < 5; k++) {
            int i = threadIdx.x + k * 256;
            if (k < 4 || i < CHUNK_) { x[k] = __ldcs(&ml[i]); s[k] = __ldg(&sp[i]); }
        }
        #pragma unroll
        for (int k = 0; k < 5; k++) {
            int i = threadIdx.x + k * 256;
            if (k == 4 && i >= CHUNK_) continue;
            bool s0 = (x[k].x > 0.f) & (s[k].x == cls);
            bool s1 = (x[k].y > 0.f) & (s[k].y == cls);
            bool s2 = (x[k].z > 0.f) & (s[k].z == cls);
            bool s3 = (x[k].w > 0.f) & (s[k].w == cls);
            float4 o;
            o.x = s0 ? 1.f : 0.f;
            o.y = s1 ? 1.f : 0.f;
            o.z = s2 ? 1.f : 0.f;
            o.w = s3 ? 1.f : 0.f;
            __stcs(&om[i], o);
            cnt += (int)s0 + (int)s1 + (int)s2 + (int)s3;
            if (s0 | s1 | s2 | s3) {
                if (s0) ssum += __fdividef(1.f, 1.f + __expf(-x[k].x));
                if (s1) ssum += __fdividef(1.f, 1.f + __expf(-x[k].y));
                if (s2) ssum += __fdividef(1.f, 1.f + __expf(-x[k].z));
                if (s3) ssum += __fdividef(1.f, 1.f + __expf(-x[k].w));
            }
        }

        // Block reduction (8 warps); fixed shuffle-tree order -> deterministic.
        __shared__ int   scnt[8];
        __shared__ float ssh[8];
        #pragma unroll
        for (int off = 16; off > 0; off >>= 1) {
            cnt  += __shfl_down_sync(0xFFFFFFFFu, cnt,  off);
            ssum += __shfl_down_sync(0xFFFFFFFFu, ssum, off);
        }
        int wid  = threadIdx.x >> 5;
        int lane = threadIdx.x & 31;
        if (lane == 0) { scnt[wid] = cnt; ssh[wid] = ssum; }
        __syncthreads();
        if (threadIdx.x == 0) {
            int tc = 0; float ts = 0.f;
            #pragma unroll
            for (int w = 0; w < 8; w++) { tc += scnt[w]; ts += ssh[w]; }
            g_part_cnt[bq][chunk] = tc;
            g_part_sum[bq][chunk] = ts;
        }
    }

    // ---- arrival: last of the row's 10 blocks does the row epilogue ----
    __shared__ int s_last;
    if (threadIdx.x == 0) {
        __threadfence();                              // publish partials
        int prev = atomicAdd(&g_arrive[bq], 1);
        s_last = (prev == S_ - 1);
    }
    __syncthreads();
    if (!s_last) return;

    __shared__ int s_flag;
    if (threadIdx.x == 0) {
        __threadfence();                              // acquire side
        int   cnt = 0;
        float sum = 0.f;
        #pragma unroll
        for (int c = 0; c < S_; c++) {
            cnt += __ldcg(&g_part_cnt[bq][c]);
            sum += __ldcg(&g_part_sum[bq][c]);
        }
        const int v = (cnt >= MIN_PTS_NUM) && (cls >= MIN_INST_CLS);
        out_cls[bq]    = (float)cls;
        out_valid[bq]  = (float)v;
        out_scores[bq] = v ? sum / (float)cnt : 0.f;
        s_flag = (!v) && (cls >= MIN_INST_CLS);
        atomicExch(&g_arrive[bq], 0);                 // replay-safe reset
    }
    __syncthreads();

    if (s_flag) {   // never with this data (cnt~1250 >> 50): safety net
        float4* __restrict__ zm = reinterpret_cast<float4*>(out_masks) + (size_t)bq * NV_;
        const float4 z = make_float4(0.f, 0.f, 0.f, 0.f);
        for (int i = threadIdx.x; i < NV_; i += 256)
            __stcs(&zm[i], z);
    }
}

// ---------------------------------------------------------------------------
extern "C" void kernel_launch(void* const* d_in, const int* in_sizes, int n_in,
                              void* d_out, int out_size)
{
    const float* mask_logits = (const float*)d_in[0];   // [B,Q,N]  fp32
    const float* cls_logits  = (const float*)d_in[1];   // [B,Q,C]  fp32
    const int*   seg_pred    = (const int*)d_in[2];     // [B,N]    int32
    const int*   fg_idxs     = (const int*)d_in[3];     // [B*N]    int32
    float* out = (float*)d_out;

    float* out_masks  = out;
    float* out_scores = out + OFF_SCORES;
    float* out_valid  = out + OFF_VALID;
    float* out_cls    = out + OFF_CLS;
    float* out_gid    = out + OFF_GID;

    dim3 grid(S_, BQ_);
    fused_kernel<<<grid, 256>>>(mask_logits, cls_logits, seg_pred, fg_idxs,
                                out_masks, out_scores, out_valid,
                                out_cls, out_gid);
}

// round 13
// speedup vs baseline: 1.0406x; 1.0406x over previous
#include <cuda_runtime.h>

// Problem shapes (fixed for this dataset entry)
#define B_   4
#define Q_   128
#define N_   50000
#define C_   20
#define BQ_  (B_ * Q_)          // 512
#define BN_  (B_ * N_)          // 200000
#define NV_  (N_ / 4)           // 12500 float4 per row
#define S_   10                 // producer chunks per row
#define CHUNK_ (NV_ / S_)       // 1250 float4 per chunk
#define NSTREAM_ 250            // threads 0..249 stream 5 float4 each (=1250)
#define GIDV_ (BN_ / 4)         // 50000 int4 for gid convert
#define GID_PER_BLK ((GIDV_ + BQ_ - 1) / BQ_)    // 98 int4 per epilogue block

#define MIN_PTS_NUM  50
#define MIN_INST_CLS 4
#define FIXSCALE 16777216.0f    // 2^24 fixed-point (deterministic u64 sum)

// Output layout (fp32 concatenation, matching reference return order)
#define OFF_SCORES ((size_t)BQ_ * N_)            // 25,600,000
#define OFF_VALID  (OFF_SCORES + BQ_)
#define OFF_CLS    (OFF_VALID + BQ_)
#define OFF_GID    (OFF_CLS + BQ_)

// Scratch (no device allocation -> __device__ globals). Accumulated via
// relaxed atomics within a launch; reset to zero by the epilogue block ->
// returns to initial state every invocation (graph-replay safe).
__device__ int                g_cnt_tot[BQ_];
__device__ unsigned long long g_sum_tot[BQ_];
__device__ unsigned int       g_arrive[BQ_];

// Inline per-row argmax over C=20 class logits. Matches jnp.argmax first-max.
__device__ __forceinline__ int row_argmax(const float* __restrict__ p)
{
    float best = __ldg(&p[0]);
    int bi = 0;
    #pragma unroll
    for (int c = 1; c < C_; c++) {
        float v = __ldg(&p[c]);
        if (v > best) { best = v; bi = c; }
    }
    return bi;
}

// ---------------------------------------------------------------------------
// Single launch, grid (S_+1, BQ_):
//  blockIdx.x < S_ : producer — one 1250-float4 chunk of row bq.
//    Threads 0..249 stream (5 float4 each, no predicates); selection is
//    sel = (logit>0)&(seg==cls) [sigmoid(x)>0.5 <=> x>0, no MUFU needed];
//    sigmoid only on selected (~2.5%). Block-reduce -> thread 250 (which has
//    issued NO global stores) publishes totals as relaxed atomics and
//    arrives with red.release.gpu: the release only drains its own two
//    ATOMGs, never the block's mask-store queue (the R11 mistake).
//  blockIdx.x == S_ : epilogue — converts its gid slice (overlapped with
//    producers), acquire-spins on the row's arrival counter, then writes
//    score/valid/cls, resets the counters (plain stores; launches
//    serialize), and cooperatively zeroes the row in the statistically
//    never-taken cnt<50 instance-class case.
// ---------------------------------------------------------------------------
__global__ __launch_bounds__(256, 6)
void fused_kernel(const float* __restrict__ mask_logits,
                  const float* __restrict__ cls_logits,
                  const int* __restrict__ seg_pred,
                  const int* __restrict__ fg_idxs,
                  float* __restrict__ out_masks,
                  float* __restrict__ out_scores,
                  float* __restrict__ out_valid,
                  float* __restrict__ out_cls,
                  float* __restrict__ out_gid)
{
    const int bq  = blockIdx.y;
    const int tid = threadIdx.x;

    if (blockIdx.x == S_) {
        // ---------------- epilogue block ----------------
        // gid convert first: useful work while producers run.
        {
            int vi = bq * GID_PER_BLK + tid;
            if (tid < GID_PER_BLK && vi < GIDV_) {
                int4 v = __ldg(&reinterpret_cast<const int4*>(fg_idxs)[vi]);
                float4 f;
                f.x = (float)v.x; f.y = (float)v.y;
                f.z = (float)v.z; f.w = (float)v.w;
                reinterpret_cast<float4*>(out_gid)[vi] = f;
            }
        }

        __shared__ int s_flag;
        if (tid == 0) {
            const unsigned int* ap = &g_arrive[bq];
            unsigned int v;
            do {
                asm volatile("ld.acquire.gpu.global.u32 %0, [%1];"
                             : "=r"(v) : "l"(ap));
                if (v < S_) __nanosleep(128);
            } while (v < S_);

            int                cnt = __ldcg(&g_cnt_tot[bq]);
            unsigned long long fs  = __ldcg(&g_sum_tot[bq]);
            const int cls = row_argmax(cls_logits + bq * C_);
            const int val = (cnt >= MIN_PTS_NUM) && (cls >= MIN_INST_CLS);
            out_cls[bq]    = (float)cls;
            out_valid[bq]  = (float)val;
            float sum = (float)((double)fs * (1.0 / 16777216.0));
            out_scores[bq] = val ? sum / (float)cnt : 0.f;
            s_flag = (!val) && (cls >= MIN_INST_CLS);
            // Reset for next replay (all producers already arrived).
            g_cnt_tot[bq] = 0;
            g_sum_tot[bq] = 0ULL;
            g_arrive[bq]  = 0u;
        }
        __syncthreads();

        if (s_flag) {   // never with this data (cnt~1250 >> 50): safety net
            float4* __restrict__ zm = reinterpret_cast<float4*>(out_masks) +
                                      (size_t)bq * NV_;
            const float4 z = make_float4(0.f, 0.f, 0.f, 0.f);
            for (int i = tid; i < NV_; i += 256)
                __stcs(&zm[i], z);
        }
        return;
    }

    // ---------------- producer block ----------------
    const int chunk = blockIdx.x;
    const int b     = bq >> 7;            // / Q_
    const int cls   = row_argmax(cls_logits + bq * C_);
    const size_t base = (size_t)bq * NV_ + (size_t)chunk * CHUNK_;

    float4* __restrict__ om = reinterpret_cast<float4*>(out_masks) + base;

    int   cnt  = 0;
    float ssum = 0.f;

    if (cls < MIN_INST_CLS) {
        const float4 z = make_float4(0.f, 0.f, 0.f, 0.f);
        if (tid < NSTREAM_) {
            #pragma unroll
            for (int k = 0; k < 5; k++)
                __stcs(&om[tid + k * NSTREAM_], z);
        }
    } else if (tid < NSTREAM_) {
        const float4* __restrict__ ml = reinterpret_cast<const float4*>(mask_logits) + base;
        const int4*   __restrict__ sp = reinterpret_cast<const int4*>(seg_pred) +
                                        (size_t)b * NV_ + (size_t)chunk * CHUNK_;

        // 5 (float4, int4) pairs, no predicates: 249+4*250 = 1249 < 1250.
        float4 x[5]; int4 s[5];
        #pragma unroll
        for (int k = 0; k < 5; k++) {
            int i = tid + k * NSTREAM_;
            x[k] = __ldcs(&ml[i]);
            s[k] = __ldg(&sp[i]);
        }
        #pragma unroll
        for (int k = 0; k < 5; k++) {
            int i = tid + k * NSTREAM_;
            bool s0 = (x[k].x > 0.f) & (s[k].x == cls);
            bool s1 = (x[k].y > 0.f) & (s[k].y == cls);
            bool s2 = (x[k].z > 0.f) & (s[k].z == cls);
            bool s3 = (x[k].w > 0.f) & (s[k].w == cls);
            float4 o;
            o.x = s0 ? 1.f : 0.f;
            o.y = s1 ? 1.f : 0.f;
            o.z = s2 ? 1.f : 0.f;
            o.w = s3 ? 1.f : 0.f;
            __stcs(&om[i], o);
            cnt += (int)s0 + (int)s1 + (int)s2 + (int)s3;
            if (s0 | s1 | s2 | s3) {
                if (s0) ssum += __fdividef(1.f, 1.f + __expf(-x[k].x));
                if (s1) ssum += __fdividef(1.f, 1.f + __expf(-x[k].y));
                if (s2) ssum += __fdividef(1.f, 1.f + __expf(-x[k].z));
                if (s3) ssum += __fdividef(1.f, 1.f + __expf(-x[k].w));
            }
        }
    }

    // Deterministic fixed-point conversion before reduction.
    unsigned long long fsum = (unsigned long long)(ssum * FIXSCALE + 0.5f);

    // Block reduction (8 warps); fixed tree -> deterministic.
    __shared__ int                scnt[8];
    __shared__ unsigned long long ssh[8];
    #pragma unroll
    for (int off = 16; off > 0; off >>= 1) {
        cnt  += __shfl_down_sync(0xFFFFFFFFu, cnt,  off);
        fsum += __shfl_down_sync(0xFFFFFFFFu, fsum, off);
    }
    int wid  = tid >> 5;
    int lane = tid & 31;
    if (lane == 0) { scnt[wid] = cnt; ssh[wid] = fsum; }
    __syncthreads();

    // Thread 250 has issued NO global stores: its release-arrive drains only
    // its own (at most two) atomics, not the mask-store queue.
    if (tid == NSTREAM_) {
        if (cls >= MIN_INST_CLS) {
            int tc = 0; unsigned long long ts = 0ULL;
            #pragma unroll
            for (int w = 0; w < 8; w++) { tc += scnt[w]; ts += ssh[w]; }
            if (tc > 0) {
                atomicAdd(&g_cnt_tot[bq], tc);      // relaxed, L2-resident
                atomicAdd(&g_sum_tot[bq], ts);
            }
        }
        asm volatile("red.release.gpu.global.add.u32 [%0], %1;"
                     :: "l"(&g_arrive[bq]), "r"(1u) : "memory");
    }
}

// ---------------------------------------------------------------------------
extern "C" void kernel_launch(void* const* d_in, const int* in_sizes, int n_in,
                              void* d_out, int out_size)
{
    const float* mask_logits = (const float*)d_in[0];   // [B,Q,N]  fp32
    const float* cls_logits  = (const float*)d_in[1];   // [B,Q,C]  fp32
    const int*   seg_pred    = (const int*)d_in[2];     // [B,N]    int32
    const int*   fg_idxs     = (const int*)d_in[3];     // [B*N]    int32
    float* out = (float*)d_out;

    float* out_masks  = out;
    float* out_scores = out + OFF_SCORES;
    float* out_valid  = out + OFF_VALID;
    float* out_cls    = out + OFF_CLS;
    float* out_gid    = out + OFF_GID;

    dim3 grid(S_ + 1, BQ_);
    fused_kernel<<<grid, 256>>>(mask_logits, cls_logits, seg_pred, fg_idxs,
                                out_masks, out_scores, out_valid,
                                out_cls, out_gid);
}